// round 9
// baseline (speedup 1.0000x reference)
#include <cuda_runtime.h>
#include <cstddef>

#define B_    256
#define T_    500
#define NIN_  128
#define NH_   512
#define NO_   64

#define HSTR   36                         // padded h row stride (floats)
#define HS_FL  (NH_ * HSTR)               // 18432 floats
#define PART_FL (16 * 32 * HSTR)          // 18432 floats
#define REC_SMEM ((HS_FL + PART_FL) * 4)  // 147456 B

// ---------------------------------------------------------------------------
// Device scratch (no runtime allocation allowed)
// ---------------------------------------------------------------------------
__device__ __align__(16) float g_h[2 * NH_ * B_];   // ping-pong hidden, k-major [k][b]
__device__ __align__(16) float g_bias[NH_];         // b_ih + b_hh
__device__ unsigned g_flag[8 * 32];                 // per-batch-group flag counters

// ---------------------------------------------------------------------------
// f32x2 packed FMA helpers
// ---------------------------------------------------------------------------
__device__ __forceinline__ unsigned long long pack2(float lo, float hi) {
    unsigned long long r;
    asm("mov.b64 %0, {%1, %2};" : "=l"(r) : "f"(lo), "f"(hi));
    return r;
}
__device__ __forceinline__ void fma2(unsigned long long& d,
                                     unsigned long long a, unsigned long long b) {
    asm("fma.rn.f32x2 %0, %1, %2, %0;" : "+l"(d) : "l"(a), "l"(b));
}
__device__ __forceinline__ float2 unpack2(unsigned long long v) {
    float2 f;
    asm("mov.b64 {%0, %1}, %2;" : "=f"(f.x), "=f"(f.y) : "l"(v));
    return f;
}

union U4 { float4 v; unsigned long long p[2]; };

// ---------------------------------------------------------------------------
// Init: transpose h0 into g_h slot 0 (k-major), fold biases, reset flags.
// <<<NH_, B_>>>
// ---------------------------------------------------------------------------
__global__ void init_kernel(const float* __restrict__ h0,
                            const float* __restrict__ b_ih,
                            const float* __restrict__ b_hh) {
    int k = blockIdx.x;
    int b = threadIdx.x;
    g_h[(size_t)k * B_ + b] = h0[(size_t)b * NH_ + k];
    if (b == 0) g_bias[k] = b_ih[k] + b_hh[k];
    if (k == 0 && b < 8) g_flag[b * 32] = 0u;
}

__global__ void nop_kernel() {}

// ---------------------------------------------------------------------------
// C[m][c] = sum_k A[m][k]*Bm[c][k] + bias[c]
// 128x64 tile, K-chunks of 32, 8x4 micro-tile per thread, f32x2 FMAs.
// ---------------------------------------------------------------------------
__global__ __launch_bounds__(256)
void gemm_bias_kernel(const float* __restrict__ A, const float* __restrict__ Bm,
                      const float* __restrict__ bias, float* __restrict__ C,
                      int K, int Ntot, int bias_mode) {
    __shared__ float xs[32][128];
    __shared__ float ws[32][64];

    const int tid = threadIdx.x;
    const int m0  = blockIdx.x * 128;
    const int c0  = blockIdx.y * 64;
    const int tx  = tid & 15;
    const int ty  = tid >> 4;

    const int arow = tid & 127, akq = tid >> 7;
    const int bcol = tid & 63,  bkh = tid >> 6;

    unsigned long long acc[16];
#pragma unroll
    for (int i = 0; i < 16; i++) acc[i] = 0ull;

    for (int kc = 0; kc < K; kc += 32) {
#pragma unroll
        for (int i = 0; i < 4; i++) {
            int kk = akq * 16 + i * 4;
            float4 v = *(const float4*)(A + (size_t)(m0 + arow) * K + kc + kk);
            xs[kk + 0][arow] = v.x; xs[kk + 1][arow] = v.y;
            xs[kk + 2][arow] = v.z; xs[kk + 3][arow] = v.w;
        }
#pragma unroll
        for (int i = 0; i < 2; i++) {
            int kk = bkh * 8 + i * 4;
            float4 v = *(const float4*)(Bm + (size_t)(c0 + bcol) * K + kc + kk);
            ws[kk + 0][bcol] = v.x; ws[kk + 1][bcol] = v.y;
            ws[kk + 2][bcol] = v.z; ws[kk + 3][bcol] = v.w;
        }
        __syncthreads();

#pragma unroll
        for (int kk = 0; kk < 32; kk++) {
            U4 a0, a1, b4;
            a0.v = *(const float4*)(&xs[kk][8 * ty]);
            a1.v = *(const float4*)(&xs[kk][8 * ty + 4]);
            b4.v = *(const float4*)(&ws[kk][4 * tx]);
            unsigned long long s0 = pack2(b4.v.x, b4.v.x);
            unsigned long long s1 = pack2(b4.v.y, b4.v.y);
            unsigned long long s2 = pack2(b4.v.z, b4.v.z);
            unsigned long long s3 = pack2(b4.v.w, b4.v.w);
            fma2(acc[0],  a0.p[0], s0); fma2(acc[1],  a0.p[1], s0);
            fma2(acc[2],  a1.p[0], s0); fma2(acc[3],  a1.p[1], s0);
            fma2(acc[4],  a0.p[0], s1); fma2(acc[5],  a0.p[1], s1);
            fma2(acc[6],  a1.p[0], s1); fma2(acc[7],  a1.p[1], s1);
            fma2(acc[8],  a0.p[0], s2); fma2(acc[9],  a0.p[1], s2);
            fma2(acc[10], a1.p[0], s2); fma2(acc[11], a1.p[1], s2);
            fma2(acc[12], a0.p[0], s3); fma2(acc[13], a0.p[1], s3);
            fma2(acc[14], a1.p[0], s3); fma2(acc[15], a1.p[1], s3);
        }
        __syncthreads();
    }

    const float* bp = bias_mode ? g_bias : bias;
    float4 bv = *(const float4*)(bp + c0 + 4 * tx);

#pragma unroll
    for (int i = 0; i < 4; i++) {
        float2 p0 = unpack2(acc[0 * 4 + i]);
        float2 p1 = unpack2(acc[1 * 4 + i]);
        float2 p2 = unpack2(acc[2 * 4 + i]);
        float2 p3 = unpack2(acc[3 * 4 + i]);
        float4 lo = make_float4(p0.x + bv.x, p1.x + bv.y, p2.x + bv.z, p3.x + bv.w);
        float4 hi = make_float4(p0.y + bv.x, p1.y + bv.y, p2.y + bv.z, p3.y + bv.w);
        size_t r0 = (size_t)(m0 + 8 * ty + 2 * i) * Ntot + c0 + 4 * tx;
        *(float4*)(C + r0)        = lo;
        *(float4*)(C + r0 + Ntot) = hi;
    }
}

// ---------------------------------------------------------------------------
// Persistent recurrence. 128 CTAs x 256 threads. CTA(gb,cg): 32 rows x 32 cols.
// One flag barrier per step; pre prefetched before the wait; flag released
// before the DRAM hidden_list write (off critical path).
// ---------------------------------------------------------------------------
__global__ __launch_bounds__(256, 1)
void rnn_rec_kernel(const float* __restrict__ W_hh, const float* __restrict__ alpha,
                    float* __restrict__ outH, float* __restrict__ outF) {
    extern __shared__ float sm[];
    float* hs   = sm;             // [512][36] k-major h tile (padded)
    float* part = sm + HS_FL;     // [16 kgroups][32 cols][36 rows-pad]

    const int tid = threadIdx.x;
    const int gb  = blockIdx.x & 7;
    const int cg  = blockIdx.x >> 3;
    unsigned* flg = &g_flag[gb * 32];

    // ---- compute role: thread (c2,g) owns cols {cg*32+2c2, +1}, k = g+16j ----
    const int c2 = tid & 15, g = tid >> 4;
    float w0[32], w1[32];
    {
        const float* wr = W_hh + (size_t)(cg * 32 + 2 * c2) * NH_;
#pragma unroll
        for (int j = 0; j < 32; j++) {
            w0[j] = wr[g + 16 * j];
            w1[j] = wr[NH_ + g + 16 * j];
        }
    }

    // ---- loader role: 16 x float4 per thread ----
    const int lq = tid & 7, lk = tid >> 3;

    // ---- reduce role: row rrow (32), col quad rcq (8 quads x 4 cols) ----
    const int rrow = tid & 31, rcq = tid >> 5;
    {
        // alpha for reduce role
    }
    float4 av = *(const float4*)(alpha + cg * 32 + 4 * rcq);
    const float al0 = av.x, al1 = av.y, al2 = av.z, al3 = av.w;
    const float om0 = 1.f - av.x, om1 = 1.f - av.y, om2 = 1.f - av.z, om3 = 1.f - av.w;

    for (int t = 0; t < T_; t++) {
        const float* hsrc = g_h + (size_t)(t & 1) * NH_ * B_;
        float*       hdst = g_h + (size_t)((t + 1) & 1) * NH_ * B_;

        // 0) prefetch pre (own slice of outH — no cross-CTA hazard) before wait
        const size_t haddr = ((size_t)(gb * 32 + rrow) * T_ + t) * NH_ +
                             cg * 32 + 4 * rcq;
        float4 pre = __ldcs((const float4*)(outH + haddr));

        // 1) wait for all 16 cg-CTAs of this batch group (step t-1 writes)
        if (t > 0) {
            if (tid == 0) {
                unsigned target = 16u * (unsigned)t, v;
                do {
                    asm volatile("ld.global.acquire.gpu.u32 %0, [%1];"
                                 : "=r"(v) : "l"(flg));
                } while (v < target);
            }
            __syncthreads();
        }

        // 2) load h tile (512 k x 32 b) k-major into padded smem
#pragma unroll
        for (int i = 0; i < 16; i++) {
            int k = lk + 32 * i;
            float4 v = __ldcg((const float4*)(hsrc + (size_t)k * B_ +
                                              gb * 32 + 4 * lq));
            *(float4*)(hs + k * HSTR + 4 * lq) = v;
        }
        __syncthreads();

        // 3) partial GEMM: 32 k per thread, 2 cols, 32 rows
        unsigned long long a0[16], a1[16];
#pragma unroll
        for (int i = 0; i < 16; i++) { a0[i] = 0ull; a1[i] = 0ull; }
#pragma unroll
        for (int j = 0; j < 32; j++) {
            const float* row = hs + (g + 16 * j) * HSTR;
            unsigned long long p0 = pack2(w0[j], w0[j]);
            unsigned long long p1 = pack2(w1[j], w1[j]);
#pragma unroll
            for (int hhalf = 0; hhalf < 2; hhalf++) {
                U4 h0, h1, h2, h3;
                h0.v = *(const float4*)(row + 16 * hhalf);
                h1.v = *(const float4*)(row + 16 * hhalf + 4);
                h2.v = *(const float4*)(row + 16 * hhalf + 8);
                h3.v = *(const float4*)(row + 16 * hhalf + 12);
                int o = 8 * hhalf;
                fma2(a0[o + 0], h0.p[0], p0); fma2(a0[o + 1], h0.p[1], p0);
                fma2(a0[o + 2], h1.p[0], p0); fma2(a0[o + 3], h1.p[1], p0);
                fma2(a0[o + 4], h2.p[0], p0); fma2(a0[o + 5], h2.p[1], p0);
                fma2(a0[o + 6], h3.p[0], p0); fma2(a0[o + 7], h3.p[1], p0);
                fma2(a1[o + 0], h0.p[0], p1); fma2(a1[o + 1], h0.p[1], p1);
                fma2(a1[o + 2], h1.p[0], p1); fma2(a1[o + 3], h1.p[1], p1);
                fma2(a1[o + 4], h2.p[0], p1); fma2(a1[o + 5], h2.p[1], p1);
                fma2(a1[o + 6], h3.p[0], p1); fma2(a1[o + 7], h3.p[1], p1);
            }
        }
        {
            float* pb0 = part + (size_t)(g * 32 + 2 * c2) * HSTR;
            float* pb1 = pb0 + HSTR;
#pragma unroll
            for (int q = 0; q < 8; q++) {
                float2 lo = unpack2(a0[2 * q]);
                float2 hi = unpack2(a0[2 * q + 1]);
                *(float4*)(pb0 + 4 * q) = make_float4(lo.x, lo.y, hi.x, hi.y);
                lo = unpack2(a1[2 * q]);
                hi = unpack2(a1[2 * q + 1]);
                *(float4*)(pb1 + 4 * q) = make_float4(lo.x, lo.y, hi.x, hi.y);
            }
        }
        __syncthreads();

        // 4) reduce 16 k-groups, add pre, relu, leaky update
        float s0 = 0.f, s1 = 0.f, s2 = 0.f, s3 = 0.f;
        {
            const float* pb = part + (size_t)(4 * rcq) * HSTR + rrow;
#pragma unroll
            for (int g2 = 0; g2 < 16; g2++) {
                const float* p = pb + (size_t)g2 * (32 * HSTR);
                s0 += p[0];
                s1 += p[HSTR];
                s2 += p[2 * HSTR];
                s3 += p[3 * HSTR];
            }
        }
        const int kc = cg * 32 + 4 * rcq;
        float c0 = fmaxf(s0 + pre.x, 0.f);
        float c1 = fmaxf(s1 + pre.y, 0.f);
        float c2v = fmaxf(s2 + pre.z, 0.f);
        float c3 = fmaxf(s3 + pre.w, 0.f);
        float h0v = om0 * hs[(kc + 0) * HSTR + rrow] + al0 * c0;
        float h1v = om1 * hs[(kc + 1) * HSTR + rrow] + al1 * c1;
        float h2v = om2 * hs[(kc + 2) * HSTR + rrow] + al2 * c2v;
        float h3v = om3 * hs[(kc + 3) * HSTR + rrow] + al3 * c3;

        // 5) publish h for next step FIRST, release flag, THEN slow DRAM writes
        const int brow = gb * 32 + rrow;
        if (t < T_ - 1) {
            __stcg(hdst + (size_t)(kc + 0) * B_ + brow, h0v);
            __stcg(hdst + (size_t)(kc + 1) * B_ + brow, h1v);
            __stcg(hdst + (size_t)(kc + 2) * B_ + brow, h2v);
            __stcg(hdst + (size_t)(kc + 3) * B_ + brow, h3v);
            __syncthreads();                       // all stores done CTA-wide
            if (tid == 0) {
                asm volatile("red.release.gpu.global.add.u32 [%0], %1;"
                             :: "l"(flg), "r"(1u) : "memory");
            }
        }
        float4 hn = make_float4(h0v, h1v, h2v, h3v);
        *(float4*)(outH + haddr) = hn;             // hidden_list (off crit path)
        if (t == T_ - 1)
            *(float4*)(outF + (size_t)brow * NH_ + kc) = hn;
    }
}

// ---------------------------------------------------------------------------
extern "C" void kernel_launch(void* const* d_in, const int* in_sizes, int n_in,
                              void* d_out, int out_size) {
    const float* x     = (const float*)d_in[0];   // [B,T,128]
    const float* h0    = (const float*)d_in[1];   // [B,512]
    const float* Wih   = (const float*)d_in[2];   // [512,128]
    const float* Whh   = (const float*)d_in[3];   // [512,512]
    const float* bih   = (const float*)d_in[4];   // [512]
    const float* bhh   = (const float*)d_in[5];   // [512]
    const float* Wout  = (const float*)d_in[6];   // [64,512]
    const float* bout  = (const float*)d_in[7];   // [64]
    const float* alpha = (const float*)d_in[8];   // [512]

    float* out  = (float*)d_out;
    float* outH = out;                                   // hidden_list [B,T,512]
    float* outO = out + (size_t)B_ * T_ * NH_;           // output_list [B,T,64]
    float* outF = outO + (size_t)B_ * T_ * NO_;          // h_final     [B,512]

    cudaFuncSetAttribute(rnn_rec_kernel,
                         cudaFuncAttributeMaxDynamicSharedMemorySize, REC_SMEM);

    // 1) init hidden transpose + bias fold + flag reset
    init_kernel<<<NH_, B_>>>(h0, bih, bhh);

    // 2) pre = x @ W_ih^T + (b_ih + b_hh), into hidden_list region (in-place)
    gemm_bias_kernel<<<dim3((B_ * T_) / 128, NH_ / 64), 256>>>(
        x, Wih, nullptr, outH, NIN_, NH_, 1);

    // 3) padding launches so ncu (-s 5 -c 1) profiles the recurrence kernel
    nop_kernel<<<1, 1>>>();
    nop_kernel<<<1, 1>>>();
    nop_kernel<<<1, 1>>>();

    // 4) 500-step recurrence, persistent (6th launch)
    rnn_rec_kernel<<<128, 256, REC_SMEM>>>(Whh, alpha, outH, outF);

    // 5) output_list = hidden_list @ W_out^T + b_out
    gemm_bias_kernel<<<dim3((B_ * T_) / 128, NO_ / 64), 256>>>(
        outH, Wout, bout, outO, NH_, NO_, 0);
}

// round 10
// speedup vs baseline: 1.3795x; 1.3795x over previous
#include <cuda_runtime.h>
#include <cstddef>

#define B_    256
#define T_    500
#define NIN_  128
#define NH_   512
#define NO_   64

#define HSTR   36                          // padded h row stride (floats)
#define HS_FL  (NH_ * HSTR)                // 18432 floats (73728 B)
#define PART_FL (8 * 32 * HSTR)            // 9216 floats  (36864 B)
#define REC_SMEM 122880                    // 120 KB request -> 1 CTA/SM

// ---------------------------------------------------------------------------
// Device scratch (no runtime allocation allowed)
// ---------------------------------------------------------------------------
__device__ __align__(16) float g_h[2 * NH_ * B_];   // ping-pong hidden, k-major [k][b]
__device__ __align__(16) float g_bias[NH_];         // b_ih + b_hh
__device__ unsigned g_flag[8 * 16 * 8];             // [gb][slice] monotonic, x8 pad

// ---------------------------------------------------------------------------
// f32x2 packed FMA helpers
// ---------------------------------------------------------------------------
__device__ __forceinline__ unsigned long long pack2(float lo, float hi) {
    unsigned long long r;
    asm("mov.b64 %0, {%1, %2};" : "=l"(r) : "f"(lo), "f"(hi));
    return r;
}
__device__ __forceinline__ void fma2(unsigned long long& d,
                                     unsigned long long a, unsigned long long b) {
    asm("fma.rn.f32x2 %0, %1, %2, %0;" : "+l"(d) : "l"(a), "l"(b));
}
__device__ __forceinline__ float2 unpack2(unsigned long long v) {
    float2 f;
    asm("mov.b64 {%0, %1}, %2;" : "=f"(f.x), "=f"(f.y) : "l"(v));
    return f;
}

union U4 { float4 v; unsigned long long p[2]; };

// ---------------------------------------------------------------------------
// Init: transpose h0 into g_h slot 0 (k-major), fold biases, reset flags.
// <<<NH_, B_>>>
// ---------------------------------------------------------------------------
__global__ void init_kernel(const float* __restrict__ h0,
                            const float* __restrict__ b_ih,
                            const float* __restrict__ b_hh) {
    int k = blockIdx.x;
    int b = threadIdx.x;
    g_h[(size_t)k * B_ + b] = h0[(size_t)b * NH_ + k];
    if (b == 0) g_bias[k] = b_ih[k] + b_hh[k];
    if (k == 0 && b < 128) g_flag[b * 8] = 0u;
}

// ---------------------------------------------------------------------------
// C[m][c] = sum_k A[m][k]*Bm[c][k] + bias[c]
// 128x64 tile, K-chunks of 32, 8x4 micro-tile per thread, f32x2 FMAs.
// ---------------------------------------------------------------------------
__global__ __launch_bounds__(256)
void gemm_bias_kernel(const float* __restrict__ A, const float* __restrict__ Bm,
                      const float* __restrict__ bias, float* __restrict__ C,
                      int K, int Ntot, int bias_mode) {
    __shared__ float xs[32][128];
    __shared__ float ws[32][64];

    const int tid = threadIdx.x;
    const int m0  = blockIdx.x * 128;
    const int c0  = blockIdx.y * 64;
    const int tx  = tid & 15;
    const int ty  = tid >> 4;

    const int arow = tid & 127, akq = tid >> 7;
    const int bcol = tid & 63,  bkh = tid >> 6;

    unsigned long long acc[16];
#pragma unroll
    for (int i = 0; i < 16; i++) acc[i] = 0ull;

    for (int kc = 0; kc < K; kc += 32) {
#pragma unroll
        for (int i = 0; i < 4; i++) {
            int kk = akq * 16 + i * 4;
            float4 v = *(const float4*)(A + (size_t)(m0 + arow) * K + kc + kk);
            xs[kk + 0][arow] = v.x; xs[kk + 1][arow] = v.y;
            xs[kk + 2][arow] = v.z; xs[kk + 3][arow] = v.w;
        }
#pragma unroll
        for (int i = 0; i < 2; i++) {
            int kk = bkh * 8 + i * 4;
            float4 v = *(const float4*)(Bm + (size_t)(c0 + bcol) * K + kc + kk);
            ws[kk + 0][bcol] = v.x; ws[kk + 1][bcol] = v.y;
            ws[kk + 2][bcol] = v.z; ws[kk + 3][bcol] = v.w;
        }
        __syncthreads();

#pragma unroll
        for (int kk = 0; kk < 32; kk++) {
            U4 a0, a1, b4;
            a0.v = *(const float4*)(&xs[kk][8 * ty]);
            a1.v = *(const float4*)(&xs[kk][8 * ty + 4]);
            b4.v = *(const float4*)(&ws[kk][4 * tx]);
            unsigned long long s0 = pack2(b4.v.x, b4.v.x);
            unsigned long long s1 = pack2(b4.v.y, b4.v.y);
            unsigned long long s2 = pack2(b4.v.z, b4.v.z);
            unsigned long long s3 = pack2(b4.v.w, b4.v.w);
            fma2(acc[0],  a0.p[0], s0); fma2(acc[1],  a0.p[1], s0);
            fma2(acc[2],  a1.p[0], s0); fma2(acc[3],  a1.p[1], s0);
            fma2(acc[4],  a0.p[0], s1); fma2(acc[5],  a0.p[1], s1);
            fma2(acc[6],  a1.p[0], s1); fma2(acc[7],  a1.p[1], s1);
            fma2(acc[8],  a0.p[0], s2); fma2(acc[9],  a0.p[1], s2);
            fma2(acc[10], a1.p[0], s2); fma2(acc[11], a1.p[1], s2);
            fma2(acc[12], a0.p[0], s3); fma2(acc[13], a0.p[1], s3);
            fma2(acc[14], a1.p[0], s3); fma2(acc[15], a1.p[1], s3);
        }
        __syncthreads();
    }

    const float* bp = bias_mode ? g_bias : bias;
    float4 bv = *(const float4*)(bp + c0 + 4 * tx);

#pragma unroll
    for (int i = 0; i < 4; i++) {
        float2 p0 = unpack2(acc[0 * 4 + i]);
        float2 p1 = unpack2(acc[1 * 4 + i]);
        float2 p2 = unpack2(acc[2 * 4 + i]);
        float2 p3 = unpack2(acc[3 * 4 + i]);
        float4 lo = make_float4(p0.x + bv.x, p1.x + bv.y, p2.x + bv.z, p3.x + bv.w);
        float4 hi = make_float4(p0.y + bv.x, p1.y + bv.y, p2.y + bv.z, p3.y + bv.w);
        size_t r0 = (size_t)(m0 + 8 * ty + 2 * i) * Ntot + c0 + 4 * tx;
        *(float4*)(C + r0)        = lo;
        *(float4*)(C + r0 + Ntot) = hi;
    }
}

// ---------------------------------------------------------------------------
// Persistent recurrence. 128 CTAs x 256 threads. CTA(gb,cg): 32 rows x 32 cols.
// Warp g consumes only k-slices 2*((g+cg)%8), +1 — gated by per-producer flags,
// no CTA-wide wait. Producer = CTA cg publishes slice cg each step.
// ---------------------------------------------------------------------------
__global__ __launch_bounds__(256, 1)
void rnn_rec_kernel(const float* __restrict__ W_hh, const float* __restrict__ alpha,
                    float* __restrict__ outH, float* __restrict__ outF) {
    extern __shared__ float sm[];
    float* hs   = sm;             // [512][36] k-major h tile (phys k positions)
    float* part = sm + HS_FL;     // [8 g][32 c][36]

    const int tid  = threadIdx.x;
    const int lane = tid & 31;
    const int gb   = blockIdx.x & 7;
    const int cg   = blockIdx.x >> 3;

    // ---- compute role: c = col within CTA, g = warp = k-group owner ----
    const int c = tid & 31, g = tid >> 5;
    const int k_base = 64 * ((g + cg) & 7);          // rotated phys k range
    const int S = (k_base >> 5);                     // first slice (2 slices)
    float w[64];
    {
        const float* wr = W_hh + (size_t)(cg * 32 + c) * NH_ + k_base;
#pragma unroll
        for (int i = 0; i < 16; i++) {
            float4 v = *(const float4*)(wr + 4 * i);
            w[4 * i] = v.x; w[4 * i + 1] = v.y; w[4 * i + 2] = v.z; w[4 * i + 3] = v.w;
        }
    }

    // ---- loader role (within warp): lq = float4 col, lk2 = k sub-row ----
    const int lq = lane & 7, lk2 = lane >> 3;

    // ---- reduce role: rrow = batch row, rcq = col quad ----
    const int rrow = tid & 31, rcq = tid >> 5;
    float4 av = *(const float4*)(alpha + cg * 32 + 4 * rcq);
    const float al0 = av.x, al1 = av.y, al2 = av.z, al3 = av.w;
    const float om0 = 1.f - av.x, om1 = 1.f - av.y, om2 = 1.f - av.z, om3 = 1.f - av.w;

    unsigned* myflag0 = &g_flag[(gb * 16 + S) * 8];
    unsigned* myflag1 = &g_flag[(gb * 16 + S + 1) * 8];
    unsigned* relflag = &g_flag[(gb * 16 + cg) * 8];

    for (int t = 0; t < T_; t++) {
        const float* hsrc = g_h + (size_t)(t & 1) * NH_ * B_;
        float*       hdst = g_h + (size_t)((t + 1) & 1) * NH_ * B_;

        // 0) prefetch pre (own slice of outH — no cross-CTA hazard)
        const size_t haddr = ((size_t)(gb * 32 + rrow) * T_ + t) * NH_ +
                             cg * 32 + 4 * rcq;
        float4 pre = __ldcg((const float4*)(outH + haddr));

        // 1) per-warp gate: wait only this warp's 2 producer flags
        if (t > 0) {
            if (lane < 2) {
                unsigned* fp = (lane == 0) ? myflag0 : myflag1;
                unsigned v;
                do {
                    asm volatile("ld.global.acquire.gpu.u32 %0, [%1];"
                                 : "=r"(v) : "l"(fp));
                } while (v < (unsigned)t);
            }
            __syncwarp();
        }

        // 2) per-warp load of its own 2 slices (64 k x 32 b) into hs
#pragma unroll
        for (int ii = 0; ii < 16; ii++) {
            int k = k_base + lk2 + 4 * ii;
            float4 v = __ldcg((const float4*)(hsrc + (size_t)k * B_ +
                                              gb * 32 + 4 * lq));
            *(float4*)(hs + (size_t)k * HSTR + 4 * lq) = v;
        }
        __syncwarp();

        // 3) partial GEMM: 64 k per thread, 1 col, 32 rows (R6 core)
        unsigned long long acc[16];
#pragma unroll
        for (int i = 0; i < 16; i++) acc[i] = 0ull;
        const float* hbase = hs + (size_t)k_base * HSTR;
#pragma unroll
        for (int kk = 0; kk < 64; kk++) {
            unsigned long long wsp = pack2(w[kk], w[kk]);
            const float* row = hbase + (size_t)kk * HSTR;
#pragma unroll
            for (int q = 0; q < 8; q++) {
                U4 hv;
                hv.v = *(const float4*)(row + 4 * q);    // broadcast
                fma2(acc[2 * q],     hv.p[0], wsp);
                fma2(acc[2 * q + 1], hv.p[1], wsp);
            }
        }
        {
            float* pb = part + (size_t)(g * 32 + c) * HSTR;
#pragma unroll
            for (int q = 0; q < 8; q++) {
                float2 lo = unpack2(acc[2 * q]);
                float2 hi = unpack2(acc[2 * q + 1]);
                *(float4*)(pb + 4 * q) = make_float4(lo.x, lo.y, hi.x, hi.y);
            }
        }
        __syncthreads();

        // 4) reduce 8 k-groups, add pre, relu, leaky update
        float s0 = 0.f, s1 = 0.f, s2 = 0.f, s3 = 0.f;
        {
            const float* pb = part + (size_t)(4 * rcq) * HSTR + rrow;
#pragma unroll
            for (int gg = 0; gg < 8; gg++) {
                const float* p = pb + (size_t)gg * (32 * HSTR);
                s0 += p[0];
                s1 += p[HSTR];
                s2 += p[2 * HSTR];
                s3 += p[3 * HSTR];
            }
        }
        const int kc = cg * 32 + 4 * rcq;                // phys col / next-step k
        float c0 = fmaxf(s0 + pre.x, 0.f);
        float c1 = fmaxf(s1 + pre.y, 0.f);
        float c2v = fmaxf(s2 + pre.z, 0.f);
        float c3 = fmaxf(s3 + pre.w, 0.f);
        float h0v = om0 * hs[(size_t)(kc + 0) * HSTR + rrow] + al0 * c0;
        float h1v = om1 * hs[(size_t)(kc + 1) * HSTR + rrow] + al1 * c1;
        float h2v = om2 * hs[(size_t)(kc + 2) * HSTR + rrow] + al2 * c2v;
        float h3v = om3 * hs[(size_t)(kc + 3) * HSTR + rrow] + al3 * c3;

        // 5) publish own h slice, release flag, THEN slow DRAM writes
        const int brow = gb * 32 + rrow;
        if (t < T_ - 1) {
            __stcg(hdst + (size_t)(kc + 0) * B_ + brow, h0v);
            __stcg(hdst + (size_t)(kc + 1) * B_ + brow, h1v);
            __stcg(hdst + (size_t)(kc + 2) * B_ + brow, h2v);
            __stcg(hdst + (size_t)(kc + 3) * B_ + brow, h3v);
        }
        __syncthreads();          // h stores done CTA-wide; hs reads done too
        if (t < T_ - 1 && tid == 0) {
            asm volatile("red.release.gpu.global.add.u32 [%0], %1;"
                         :: "l"(relflag), "r"(1u) : "memory");
        }
        float4 hn = make_float4(h0v, h1v, h2v, h3v);
        *(float4*)(outH + haddr) = hn;                   // hidden_list (off path)
        if (t == T_ - 1)
            *(float4*)(outF + (size_t)brow * NH_ + kc) = hn;
    }
}

// ---------------------------------------------------------------------------
extern "C" void kernel_launch(void* const* d_in, const int* in_sizes, int n_in,
                              void* d_out, int out_size) {
    const float* x     = (const float*)d_in[0];   // [B,T,128]
    const float* h0    = (const float*)d_in[1];   // [B,512]
    const float* Wih   = (const float*)d_in[2];   // [512,128]
    const float* Whh   = (const float*)d_in[3];   // [512,512]
    const float* bih   = (const float*)d_in[4];   // [512]
    const float* bhh   = (const float*)d_in[5];   // [512]
    const float* Wout  = (const float*)d_in[6];   // [64,512]
    const float* bout  = (const float*)d_in[7];   // [64]
    const float* alpha = (const float*)d_in[8];   // [512]

    float* out  = (float*)d_out;
    float* outH = out;                                   // hidden_list [B,T,512]
    float* outO = out + (size_t)B_ * T_ * NH_;           // output_list [B,T,64]
    float* outF = outO + (size_t)B_ * T_ * NO_;          // h_final     [B,512]

    cudaFuncSetAttribute(rnn_rec_kernel,
                         cudaFuncAttributeMaxDynamicSharedMemorySize, REC_SMEM);

    // 1) init hidden transpose + bias fold + flag reset
    init_kernel<<<NH_, B_>>>(h0, bih, bhh);

    // 2) pre = x @ W_ih^T + (b_ih + b_hh), into hidden_list region (in-place)
    gemm_bias_kernel<<<dim3((B_ * T_) / 128, NH_ / 64), 256>>>(
        x, Wih, nullptr, outH, NIN_, NH_, 1);

    // 3) 500-step recurrence, persistent, per-warp slice gating
    rnn_rec_kernel<<<128, 256, REC_SMEM>>>(Whh, alpha, outH, outF);

    // 4) output_list = hidden_list @ W_out^T + b_out
    gemm_bias_kernel<<<dim3((B_ * T_) / 128, NO_ / 64), 256>>>(
        outH, Wout, bout, outO, NH_, NO_, 0);
}

// round 11
// speedup vs baseline: 1.6652x; 1.2072x over previous
#include <cuda_runtime.h>
#include <cstddef>

#define B_    256
#define T_    500
#define NIN_  128
#define NH_   512
#define NO_   64

#define HSTR   36                          // padded h row stride (floats)
#define HS_FL  (NH_ * HSTR)                // 18432 floats (73728 B)
#define PART_FL (8 * 32 * HSTR)            // 9216 floats  (36864 B)
#define REC_SMEM 122880                    // 120 KB request -> 1 CTA/SM

// ---------------------------------------------------------------------------
// Device scratch (no runtime allocation allowed)
// ---------------------------------------------------------------------------
__device__ __align__(16) float g_h[2 * NH_ * B_];   // ping-pong hidden, k-major [k][b]
__device__ __align__(16) float g_bias[NH_];         // b_ih + b_hh
__device__ unsigned g_flag[8 * 16 * 8];             // [gb][slice] monotonic, x8 pad

// ---------------------------------------------------------------------------
// f32x2 packed FMA helpers
// ---------------------------------------------------------------------------
__device__ __forceinline__ unsigned long long pack2(float lo, float hi) {
    unsigned long long r;
    asm("mov.b64 %0, {%1, %2};" : "=l"(r) : "f"(lo), "f"(hi));
    return r;
}
__device__ __forceinline__ void fma2(unsigned long long& d,
                                     unsigned long long a, unsigned long long b) {
    asm("fma.rn.f32x2 %0, %1, %2, %0;" : "+l"(d) : "l"(a), "l"(b));
}
__device__ __forceinline__ float2 unpack2(unsigned long long v) {
    float2 f;
    asm("mov.b64 {%0, %1}, %2;" : "=f"(f.x), "=f"(f.y) : "l"(v));
    return f;
}

union U4 { float4 v; unsigned long long p[2]; };

// ---------------------------------------------------------------------------
// Init: transpose h0 into g_h slot 0 (k-major), fold biases, reset flags.
// <<<NH_, B_>>>
// ---------------------------------------------------------------------------
__global__ void init_kernel(const float* __restrict__ h0,
                            const float* __restrict__ b_ih,
                            const float* __restrict__ b_hh) {
    int k = blockIdx.x;
    int b = threadIdx.x;
    g_h[(size_t)k * B_ + b] = h0[(size_t)b * NH_ + k];
    if (b == 0) g_bias[k] = b_ih[k] + b_hh[k];
    if (k == 0 && b < 128) g_flag[b * 8] = 0u;
}

// ---------------------------------------------------------------------------
// C[m][c] = sum_k A[m][k]*Bm[c][k] + bias[c]
// 128x64 tile, K-chunks of 32, 8x4 micro-tile per thread, f32x2 FMAs.
// ---------------------------------------------------------------------------
__global__ __launch_bounds__(256)
void gemm_bias_kernel(const float* __restrict__ A, const float* __restrict__ Bm,
                      const float* __restrict__ bias, float* __restrict__ C,
                      int K, int Ntot, int bias_mode) {
    __shared__ float xs[32][128];
    __shared__ float ws[32][64];

    const int tid = threadIdx.x;
    const int m0  = blockIdx.x * 128;
    const int c0  = blockIdx.y * 64;
    const int tx  = tid & 15;
    const int ty  = tid >> 4;

    const int arow = tid & 127, akq = tid >> 7;
    const int bcol = tid & 63,  bkh = tid >> 6;

    unsigned long long acc[16];
#pragma unroll
    for (int i = 0; i < 16; i++) acc[i] = 0ull;

    for (int kc = 0; kc < K; kc += 32) {
#pragma unroll
        for (int i = 0; i < 4; i++) {
            int kk = akq * 16 + i * 4;
            float4 v = *(const float4*)(A + (size_t)(m0 + arow) * K + kc + kk);
            xs[kk + 0][arow] = v.x; xs[kk + 1][arow] = v.y;
            xs[kk + 2][arow] = v.z; xs[kk + 3][arow] = v.w;
        }
#pragma unroll
        for (int i = 0; i < 2; i++) {
            int kk = bkh * 8 + i * 4;
            float4 v = *(const float4*)(Bm + (size_t)(c0 + bcol) * K + kc + kk);
            ws[kk + 0][bcol] = v.x; ws[kk + 1][bcol] = v.y;
            ws[kk + 2][bcol] = v.z; ws[kk + 3][bcol] = v.w;
        }
        __syncthreads();

#pragma unroll
        for (int kk = 0; kk < 32; kk++) {
            U4 a0, a1, b4;
            a0.v = *(const float4*)(&xs[kk][8 * ty]);
            a1.v = *(const float4*)(&xs[kk][8 * ty + 4]);
            b4.v = *(const float4*)(&ws[kk][4 * tx]);
            unsigned long long s0 = pack2(b4.v.x, b4.v.x);
            unsigned long long s1 = pack2(b4.v.y, b4.v.y);
            unsigned long long s2 = pack2(b4.v.z, b4.v.z);
            unsigned long long s3 = pack2(b4.v.w, b4.v.w);
            fma2(acc[0],  a0.p[0], s0); fma2(acc[1],  a0.p[1], s0);
            fma2(acc[2],  a1.p[0], s0); fma2(acc[3],  a1.p[1], s0);
            fma2(acc[4],  a0.p[0], s1); fma2(acc[5],  a0.p[1], s1);
            fma2(acc[6],  a1.p[0], s1); fma2(acc[7],  a1.p[1], s1);
            fma2(acc[8],  a0.p[0], s2); fma2(acc[9],  a0.p[1], s2);
            fma2(acc[10], a1.p[0], s2); fma2(acc[11], a1.p[1], s2);
            fma2(acc[12], a0.p[0], s3); fma2(acc[13], a0.p[1], s3);
            fma2(acc[14], a1.p[0], s3); fma2(acc[15], a1.p[1], s3);
        }
        __syncthreads();
    }

    const float* bp = bias_mode ? g_bias : bias;
    float4 bv = *(const float4*)(bp + c0 + 4 * tx);

#pragma unroll
    for (int i = 0; i < 4; i++) {
        float2 p0 = unpack2(acc[0 * 4 + i]);
        float2 p1 = unpack2(acc[1 * 4 + i]);
        float2 p2 = unpack2(acc[2 * 4 + i]);
        float2 p3 = unpack2(acc[3 * 4 + i]);
        float4 lo = make_float4(p0.x + bv.x, p1.x + bv.y, p2.x + bv.z, p3.x + bv.w);
        float4 hi = make_float4(p0.y + bv.x, p1.y + bv.y, p2.y + bv.z, p3.y + bv.w);
        size_t r0 = (size_t)(m0 + 8 * ty + 2 * i) * Ntot + c0 + 4 * tx;
        *(float4*)(C + r0)        = lo;
        *(float4*)(C + r0 + Ntot) = hi;
    }
}

// ---------------------------------------------------------------------------
// Persistent recurrence. 128 CTAs x 256 threads. CTA(gb,cg): 32 rows x 32 cols.
// Warp g owns k-slice 64*((g+cg)&7); per-producer flag gating (no CTA barrier).
// Thread micro-tile: 2 cols x 16 rows x 64 k -> 4 FFMA2 per broadcast LDS.128.
// ---------------------------------------------------------------------------
__global__ __launch_bounds__(256, 1)
void rnn_rec_kernel(const float* __restrict__ W_hh, const float* __restrict__ alpha,
                    float* __restrict__ outH, float* __restrict__ outF) {
    extern __shared__ float sm[];
    float* hs   = sm;             // [512][36] k-major h tile
    float* part = sm + HS_FL;     // [8 g][32 c][36]

    const int tid  = threadIdx.x;
    const int lane = tid & 31;
    const int gb   = blockIdx.x & 7;
    const int cg   = blockIdx.x >> 3;
    const int g    = tid >> 5;                       // warp id

    // ---- compute role: c2 = col pair (16), rh = row half (2) ----
    const int c2 = lane & 15, rh = lane >> 4;
    const int k_base = 64 * ((g + cg) & 7);          // rotated phys k range
    const int S = (k_base >> 5);                     // first 32-k slice index
    float w0[64], w1[64];
    {
        const float* wr0 = W_hh + (size_t)(cg * 32 + 2 * c2) * NH_ + k_base;
        const float* wr1 = wr0 + NH_;
#pragma unroll
        for (int i = 0; i < 16; i++) {
            float4 v0 = *(const float4*)(wr0 + 4 * i);
            float4 v1 = *(const float4*)(wr1 + 4 * i);
            w0[4 * i] = v0.x; w0[4 * i + 1] = v0.y; w0[4 * i + 2] = v0.z; w0[4 * i + 3] = v0.w;
            w1[4 * i] = v1.x; w1[4 * i + 1] = v1.y; w1[4 * i + 2] = v1.z; w1[4 * i + 3] = v1.w;
        }
    }

    // ---- loader role (within warp) ----
    const int lq = lane & 7, lk2 = lane >> 3;

    // ---- reduce role: rrow = batch row, rcq = col quad ----
    const int rrow = tid & 31, rcq = tid >> 5;
    float4 av = *(const float4*)(alpha + cg * 32 + 4 * rcq);
    const float al0 = av.x, al1 = av.y, al2 = av.z, al3 = av.w;
    const float om0 = 1.f - av.x, om1 = 1.f - av.y, om2 = 1.f - av.z, om3 = 1.f - av.w;

    unsigned* myflag0 = &g_flag[(gb * 16 + S) * 8];
    unsigned* myflag1 = &g_flag[(gb * 16 + S + 1) * 8];
    unsigned* relflag = &g_flag[(gb * 16 + cg) * 8];

    for (int t = 0; t < T_; t++) {
        const float* hsrc = g_h + (size_t)(t & 1) * NH_ * B_;
        float*       hdst = g_h + (size_t)((t + 1) & 1) * NH_ * B_;

        // 0) prefetch pre (own slice of outH — no cross-CTA hazard)
        const size_t haddr = ((size_t)(gb * 32 + rrow) * T_ + t) * NH_ +
                             cg * 32 + 4 * rcq;
        float4 pre = __ldcg((const float4*)(outH + haddr));

        // 1) per-warp gate: wait only this warp's 2 producer flags
        if (t > 0) {
            if (lane < 2) {
                unsigned* fp = (lane == 0) ? myflag0 : myflag1;
                unsigned v;
                do {
                    asm volatile("ld.global.acquire.gpu.u32 %0, [%1];"
                                 : "=r"(v) : "l"(fp));
                } while (v < (unsigned)t);
            }
            __syncwarp();
        }

        // 2) per-warp load of its own slice (64 k x 32 b) into hs
#pragma unroll
        for (int ii = 0; ii < 16; ii++) {
            int k = k_base + lk2 + 4 * ii;
            float4 v = __ldcg((const float4*)(hsrc + (size_t)k * B_ +
                                              gb * 32 + 4 * lq));
            *(float4*)(hs + (size_t)k * HSTR + 4 * lq) = v;
        }
        __syncwarp();

        // 3) partial GEMM: 64 k, 2 cols, 16 rows per thread
        unsigned long long a0[8], a1[8];   // [2q, 2q+1] per col
#pragma unroll
        for (int i = 0; i < 8; i++) { a0[i] = 0ull; a1[i] = 0ull; }
        const float* hbase = hs + (size_t)k_base * HSTR + 16 * rh;
#pragma unroll
        for (int kk = 0; kk < 64; kk++) {
            unsigned long long p0 = pack2(w0[kk], w0[kk]);
            unsigned long long p1 = pack2(w1[kk], w1[kk]);
            const float* row = hbase + (size_t)kk * HSTR;
#pragma unroll
            for (int q = 0; q < 4; q++) {
                U4 hv;
                hv.v = *(const float4*)(row + 4 * q);    // 1 wavefront (2 grp bcast)
                fma2(a0[2 * q],     hv.p[0], p0);
                fma2(a0[2 * q + 1], hv.p[1], p0);
                fma2(a1[2 * q],     hv.p[0], p1);
                fma2(a1[2 * q + 1], hv.p[1], p1);
            }
        }
        {
            float* pb0 = part + (size_t)(g * 32 + 2 * c2) * HSTR + 16 * rh;
            float* pb1 = pb0 + HSTR;
#pragma unroll
            for (int q = 0; q < 4; q++) {
                float2 lo = unpack2(a0[2 * q]);
                float2 hi = unpack2(a0[2 * q + 1]);
                *(float4*)(pb0 + 4 * q) = make_float4(lo.x, lo.y, hi.x, hi.y);
                lo = unpack2(a1[2 * q]);
                hi = unpack2(a1[2 * q + 1]);
                *(float4*)(pb1 + 4 * q) = make_float4(lo.x, lo.y, hi.x, hi.y);
            }
        }
        __syncthreads();

        // 4) reduce 8 k-groups, add pre, relu, leaky update
        float s0 = 0.f, s1 = 0.f, s2 = 0.f, s3 = 0.f;
        {
            const float* pb = part + (size_t)(4 * rcq) * HSTR + rrow;
#pragma unroll
            for (int gg = 0; gg < 8; gg++) {
                const float* p = pb + (size_t)gg * (32 * HSTR);
                s0 += p[0];
                s1 += p[HSTR];
                s2 += p[2 * HSTR];
                s3 += p[3 * HSTR];
            }
        }
        const int kc = cg * 32 + 4 * rcq;                // phys col / next-step k
        float c0 = fmaxf(s0 + pre.x, 0.f);
        float c1 = fmaxf(s1 + pre.y, 0.f);
        float c2v = fmaxf(s2 + pre.z, 0.f);
        float c3 = fmaxf(s3 + pre.w, 0.f);
        float h0v = om0 * hs[(size_t)(kc + 0) * HSTR + rrow] + al0 * c0;
        float h1v = om1 * hs[(size_t)(kc + 1) * HSTR + rrow] + al1 * c1;
        float h2v = om2 * hs[(size_t)(kc + 2) * HSTR + rrow] + al2 * c2v;
        float h3v = om3 * hs[(size_t)(kc + 3) * HSTR + rrow] + al3 * c3;

        // 5) publish own h slice, release flag, THEN slow DRAM writes
        const int brow = gb * 32 + rrow;
        if (t < T_ - 1) {
            __stcg(hdst + (size_t)(kc + 0) * B_ + brow, h0v);
            __stcg(hdst + (size_t)(kc + 1) * B_ + brow, h1v);
            __stcg(hdst + (size_t)(kc + 2) * B_ + brow, h2v);
            __stcg(hdst + (size_t)(kc + 3) * B_ + brow, h3v);
        }
        __syncthreads();          // h stores done CTA-wide; hs reads done too
        if (t < T_ - 1 && tid == 0) {
            asm volatile("red.release.gpu.global.add.u32 [%0], %1;"
                         :: "l"(relflag), "r"(1u) : "memory");
        }
        float4 hn = make_float4(h0v, h1v, h2v, h3v);
        *(float4*)(outH + haddr) = hn;                   // hidden_list (off path)
        if (t == T_ - 1)
            *(float4*)(outF + (size_t)brow * NH_ + kc) = hn;
    }
}

// ---------------------------------------------------------------------------
extern "C" void kernel_launch(void* const* d_in, const int* in_sizes, int n_in,
                              void* d_out, int out_size) {
    const float* x     = (const float*)d_in[0];   // [B,T,128]
    const float* h0    = (const float*)d_in[1];   // [B,512]
    const float* Wih   = (const float*)d_in[2];   // [512,128]
    const float* Whh   = (const float*)d_in[3];   // [512,512]
    const float* bih   = (const float*)d_in[4];   // [512]
    const float* bhh   = (const float*)d_in[5];   // [512]
    const float* Wout  = (const float*)d_in[6];   // [64,512]
    const float* bout  = (const float*)d_in[7];   // [64]
    const float* alpha = (const float*)d_in[8];   // [512]

    float* out  = (float*)d_out;
    float* outH = out;                                   // hidden_list [B,T,512]
    float* outO = out + (size_t)B_ * T_ * NH_;           // output_list [B,T,64]
    float* outF = outO + (size_t)B_ * T_ * NO_;          // h_final     [B,512]

    cudaFuncSetAttribute(rnn_rec_kernel,
                         cudaFuncAttributeMaxDynamicSharedMemorySize, REC_SMEM);

    // 1) init hidden transpose + bias fold + flag reset
    init_kernel<<<NH_, B_>>>(h0, bih, bhh);

    // 2) pre = x @ W_ih^T + (b_ih + b_hh), into hidden_list region (in-place)
    gemm_bias_kernel<<<dim3((B_ * T_) / 128, NH_ / 64), 256>>>(
        x, Wih, nullptr, outH, NIN_, NH_, 1);

    // 3) 500-step recurrence, persistent, per-warp slice gating
    rnn_rec_kernel<<<128, 256, REC_SMEM>>>(Whh, alpha, outH, outF);

    // 4) output_list = hidden_list @ W_out^T + b_out
    gemm_bias_kernel<<<dim3((B_ * T_) / 128, NO_ / 64), 256>>>(
        outH, Wout, bout, outO, NH_, NO_, 0);
}